// round 2
// baseline (speedup 1.0000x reference)
#include <cuda_runtime.h>
#include <cuda_fp16.h>
#include <cstdint>

// ---------------- problem constants ----------------
#define TOKENS 8192
#define INF    4096
#define OUTF   4096

// ---------------- GEMM tiling ----------------
#define BM 128
#define BN 128
#define BK 64
#define STAGES 4
#define KITERS (INF / BK)                  // 64
#define A_BYTES (BM * BK * 2)              // 16 KB
#define B_BYTES (BN * BK * 2)              // 16 KB
#define STAGE_BYTES (A_BYTES + B_BYTES)    // 32 KB
#define SMEM_DYN (STAGES * STAGE_BYTES + 1024)

// ---------------- device scratch (statics, no allocs) ----------------
static __device__ __half g_x16[(size_t)TOKENS * INF];  // 64 MB
static __device__ __half g_w16[(size_t)OUTF * INF];    // 32 MB
static __device__ int    g_tag[(size_t)OUTF * INF];    // 64 MB

// ---------------- helpers ----------------
__device__ __forceinline__ uint32_t smem_u32(const void* p) {
    uint32_t a;
    asm("{ .reg .u64 t; cvta.to.shared.u64 t, %1; cvt.u32.u64 %0, t; }"
        : "=r"(a) : "l"(p));
    return a;
}

#define SWZ(o) ((o) ^ (((o) >> 3) & 0x70))

__device__ __forceinline__ void cp_async16(uint32_t saddr, const void* gptr) {
    uint64_t g = __cvta_generic_to_global((void*)gptr);
    asm volatile("cp.async.cg.shared.global [%0], [%1], 16;" :: "r"(saddr), "l"(g) : "memory");
}
#define CP_COMMIT() asm volatile("cp.async.commit_group;" ::: "memory")
#define CP_WAIT(n)  asm volatile("cp.async.wait_group %0;" :: "n"(n) : "memory")

__device__ __forceinline__ void ldsm_x4(uint32_t (&r)[4], uint32_t addr) {
    asm volatile("ldmatrix.sync.aligned.m8n8.x4.shared.b16 {%0,%1,%2,%3}, [%4];"
                 : "=r"(r[0]), "=r"(r[1]), "=r"(r[2]), "=r"(r[3]) : "r"(addr));
}

__device__ __forceinline__ void mma16816(float (&d)[4], const uint32_t (&a)[4],
                                         uint32_t b0, uint32_t b1) {
    asm volatile(
        "mma.sync.aligned.m16n8k16.row.col.f32.f16.f16.f32 "
        "{%0,%1,%2,%3}, {%4,%5,%6,%7}, {%8,%9}, {%0,%1,%2,%3};"
        : "+f"(d[0]), "+f"(d[1]), "+f"(d[2]), "+f"(d[3])
        : "r"(a[0]), "r"(a[1]), "r"(a[2]), "r"(a[3]), "r"(b0), "r"(b1));
}

// ---------------- prep kernels ----------------
__global__ void prep_zero() {
    size_t stride = (size_t)gridDim.x * blockDim.x;
    size_t i = (size_t)blockIdx.x * blockDim.x + threadIdx.x;
    uint4 z = {0u, 0u, 0u, 0u};
    uint4* t = reinterpret_cast<uint4*>(g_tag);
    for (size_t j = i; j < (size_t)OUTF * INF / 4; j += stride) t[j] = z;
    uint4* w = reinterpret_cast<uint4*>(g_w16);
    for (size_t j = i; j < (size_t)OUTF * INF / 8; j += stride) w[j] = z;
}

__global__ void scatter_tag(const int* __restrict__ ridx, const int* __restrict__ cidx, int nnz) {
    int i = blockIdx.x * blockDim.x + threadIdx.x;
    if (i < nnz) {
        size_t pos = (size_t)ridx[i] * INF + cidx[i];
        atomicMax(&g_tag[pos], i + 1);
    }
}

__global__ void scatter_write(const int* __restrict__ ridx, const int* __restrict__ cidx,
                              const float* __restrict__ w, int nnz) {
    int i = blockIdx.x * blockDim.x + threadIdx.x;
    if (i < nnz) {
        size_t pos = (size_t)ridx[i] * INF + cidx[i];
        if (g_tag[pos] == i + 1) g_w16[pos] = __float2half_rn(w[i]);
    }
}

__global__ void convert_x(const float* __restrict__ x) {
    size_t stride = (size_t)gridDim.x * blockDim.x;
    size_t n4 = (size_t)TOKENS * INF / 4;
    const float4* xv = reinterpret_cast<const float4*>(x);
    __half2* xo = reinterpret_cast<__half2*>(g_x16);
    for (size_t j = (size_t)blockIdx.x * blockDim.x + threadIdx.x; j < n4; j += stride) {
        float4 v = xv[j];
        xo[2 * j + 0] = __floats2half2_rn(v.x, v.y);
        xo[2 * j + 1] = __floats2half2_rn(v.z, v.w);
    }
}

// ---------------- GEMM: out[m,n] = sum_k x16[m,k]*w16[n,k] + bias[n] ----------------
// 256 threads = 8 warps in 2(m) x 4(n); warp tile 64x32 via m16n8k16.
__global__ void __launch_bounds__(256)
gemm_kernel(const float* __restrict__ bias, float* __restrict__ out) {
    extern __shared__ char smem_raw[];
    uint32_t sbase = (smem_u32(smem_raw) + 1023u) & ~1023u;

    const int tid  = threadIdx.x;
    const int lane = tid & 31;
    const int wid  = tid >> 5;
    const int warp_m = wid & 1;   // 0..1  -> 64 rows each
    const int warp_n = wid >> 1;  // 0..3  -> 32 cols each

    // rasterization: 64 m-tiles x 32 n-tiles; groups of 8 n-tiles (512 CTAs)
    // keep an 8 MB B panel L2-resident while A streams.
    const int bid = blockIdx.x;
    const int grp = bid >> 9;               // / 512
    const int within = bid & 511;
    const int bm = within & 63;
    const int bn = (grp << 3) + (within >> 6);

    const __half* Abase = g_x16 + (size_t)bm * BM * INF;
    const __half* Bbase = g_w16 + (size_t)bn * BN * INF;

    float acc[4][4][4];
    #pragma unroll
    for (int i = 0; i < 4; ++i)
        #pragma unroll
        for (int j = 0; j < 4; ++j)
            #pragma unroll
            for (int k = 0; k < 4; ++k) acc[i][j][k] = 0.f;

    auto fill_stage = [&](int stage, int kblk) {
        const int k0 = kblk * BK;
        uint32_t sa = sbase + stage * STAGE_BYTES;
        // A: 128 rows x 128 B  (512 chunks of 16B), 256 threads -> 2 iters
        #pragma unroll
        for (int q = tid; q < (BM * BK * 2) / 16; q += 256) {
            int r = q >> 3, cb = (q & 7) * 16;
            cp_async16(sa + SWZ(r * 128 + cb), Abase + (size_t)r * INF + k0 + (q & 7) * 8);
        }
        uint32_t sb = sa + A_BYTES;
        #pragma unroll
        for (int q = tid; q < (BN * BK * 2) / 16; q += 256) {
            int r = q >> 3, cb = (q & 7) * 16;
            cp_async16(sb + SWZ(r * 128 + cb), Bbase + (size_t)r * INF + k0 + (q & 7) * 8);
        }
    };

    // prologue
    #pragma unroll
    for (int b = 0; b < STAGES - 1; ++b) { fill_stage(b, b); CP_COMMIT(); }

    // ldmatrix lane address components (within tile, pre-swizzle)
    const int a_row_l = ((lane >> 3) & 1) * 8 + (lane & 7);  // m within 16
    const int a_koff  = ((lane >> 4) & 1) * 8;               // k within 16
    const int b_row_l = ((lane >> 4) & 1) * 8 + (lane & 7);  // n within 16
    const int b_koff  = ((lane >> 3) & 1) * 8;               // k within 16

    for (int c = 0; c < KITERS; ++c) {
        CP_WAIT(STAGES - 2);
        __syncthreads();

        const int nf = c + STAGES - 1;
        if (nf < KITERS) fill_stage(nf & (STAGES - 1), nf);
        CP_COMMIT();

        const int sc = c & (STAGES - 1);
        uint32_t sa = sbase + sc * STAGE_BYTES;
        uint32_t sb = sa + A_BYTES;

        #pragma unroll
        for (int ks = 0; ks < BK / 16; ++ks) {
            uint32_t afr[4][4];
            #pragma unroll
            for (int mt = 0; mt < 4; ++mt) {
                int row = warp_m * 64 + mt * 16 + a_row_l;
                int col = ks * 16 + a_koff;
                ldsm_x4(afr[mt], sa + SWZ(row * 128 + col * 2));
            }
            uint32_t bfr[2][4];
            #pragma unroll
            for (int h = 0; h < 2; ++h) {
                int row = warp_n * 32 + h * 16 + b_row_l;
                int col = ks * 16 + b_koff;
                ldsm_x4(bfr[h], sb + SWZ(row * 128 + col * 2));
            }
            #pragma unroll
            for (int mt = 0; mt < 4; ++mt)
                #pragma unroll
                for (int nt = 0; nt < 4; ++nt)
                    mma16816(acc[mt][nt], afr[mt],
                             bfr[nt >> 1][(nt & 1) * 2], bfr[nt >> 1][(nt & 1) * 2 + 1]);
        }
    }

    // epilogue: fused bias, float2 stores
    const int gr = lane >> 2;        // 0..7
    const int gc = (lane & 3) * 2;   // 0,2,4,6
    #pragma unroll
    for (int mt = 0; mt < 4; ++mt) {
        int row0 = bm * BM + warp_m * 64 + mt * 16 + gr;
        #pragma unroll
        for (int nt = 0; nt < 4; ++nt) {
            int col = bn * BN + warp_n * 32 + nt * 8 + gc;
            float2 b2 = *reinterpret_cast<const float2*>(bias + col);
            float2 v0 = {acc[mt][nt][0] + b2.x, acc[mt][nt][1] + b2.y};
            float2 v1 = {acc[mt][nt][2] + b2.x, acc[mt][nt][3] + b2.y};
            *reinterpret_cast<float2*>(out + (size_t)row0 * OUTF + col) = v0;
            *reinterpret_cast<float2*>(out + (size_t)(row0 + 8) * OUTF + col) = v1;
        }
    }
}

// ---------------- launch ----------------
extern "C" void kernel_launch(void* const* d_in, const int* in_sizes, int n_in,
                              void* d_out, int out_size) {
    const float* x    = (const float*)d_in[0];
    const float* w    = (const float*)d_in[1];
    const float* bias = (const float*)d_in[2];
    const int*   ridx = (const int*)d_in[3];
    const int*   cidx = (const int*)d_in[4];
    float* out = (float*)d_out;
    const int nnz = in_sizes[1];

    cudaFuncSetAttribute(gemm_kernel, cudaFuncAttributeMaxDynamicSharedMemorySize, SMEM_DYN);

    prep_zero<<<1024, 256>>>();
    scatter_tag<<<(nnz + 255) / 256, 256>>>(ridx, cidx, nnz);
    scatter_write<<<(nnz + 255) / 256, 256>>>(ridx, cidx, w, nnz);
    convert_x<<<2048, 256>>>(x);

    dim3 grid((TOKENS / BM) * (OUTF / BN));   // 64 * 32 = 2048 CTAs
    gemm_kernel<<<grid, 256, SMEM_DYN>>>(bias, out);
}

// round 3
// speedup vs baseline: 1.0567x; 1.0567x over previous
#include <cuda_runtime.h>
#include <cuda_fp16.h>
#include <cstdint>

// ---------------- problem constants ----------------
#define TOKENS 8192
#define INF    4096
#define OUTF   4096

// ---------------- GEMM tiling ----------------
#define BM 256
#define BN 128
#define BK 64
#define STAGES 4
#define KITERS (INF / BK)                  // 64
#define A_BYTES (BM * BK * 2)              // 32 KB
#define B_BYTES (BN * BK * 2)              // 16 KB
#define STAGE_BYTES (A_BYTES + B_BYTES)    // 48 KB
#define SMEM_DYN (STAGES * STAGE_BYTES + 1024)   // ~193 KB

// ---------------- device scratch (statics, no allocs) ----------------
static __device__ __half g_x16[(size_t)TOKENS * INF];  // 64 MB
static __device__ __half g_w16[(size_t)OUTF * INF];    // 32 MB
static __device__ int    g_tag[(size_t)OUTF * INF];    // 64 MB

// ---------------- helpers ----------------
__device__ __forceinline__ uint32_t smem_u32(const void* p) {
    uint32_t a;
    asm("{ .reg .u64 t; cvta.to.shared.u64 t, %1; cvt.u32.u64 %0, t; }"
        : "=r"(a) : "l"(p));
    return a;
}

#define SWZ(o) ((o) ^ (((o) >> 3) & 0x70))

__device__ __forceinline__ void cp_async16(uint32_t saddr, const void* gptr) {
    uint64_t g = __cvta_generic_to_global((void*)gptr);
    asm volatile("cp.async.cg.shared.global [%0], [%1], 16;" :: "r"(saddr), "l"(g) : "memory");
}
#define CP_COMMIT() asm volatile("cp.async.commit_group;" ::: "memory")
#define CP_WAIT(n)  asm volatile("cp.async.wait_group %0;" :: "n"(n) : "memory")

__device__ __forceinline__ void ldsm_x4(uint32_t (&r)[4], uint32_t addr) {
    asm volatile("ldmatrix.sync.aligned.m8n8.x4.shared.b16 {%0,%1,%2,%3}, [%4];"
                 : "=r"(r[0]), "=r"(r[1]), "=r"(r[2]), "=r"(r[3]) : "r"(addr));
}

__device__ __forceinline__ void mma16816(float (&d)[4], const uint32_t (&a)[4],
                                         uint32_t b0, uint32_t b1) {
    asm volatile(
        "mma.sync.aligned.m16n8k16.row.col.f32.f16.f16.f32 "
        "{%0,%1,%2,%3}, {%4,%5,%6,%7}, {%8,%9}, {%0,%1,%2,%3};"
        : "+f"(d[0]), "+f"(d[1]), "+f"(d[2]), "+f"(d[3])
        : "r"(a[0]), "r"(a[1]), "r"(a[2]), "r"(a[3]), "r"(b0), "r"(b1));
}

// ---------------- prep kernels ----------------
__global__ void prep_zero() {
    size_t stride = (size_t)gridDim.x * blockDim.x;
    size_t i = (size_t)blockIdx.x * blockDim.x + threadIdx.x;
    uint4 z = {0u, 0u, 0u, 0u};
    uint4* t = reinterpret_cast<uint4*>(g_tag);
    for (size_t j = i; j < (size_t)OUTF * INF / 4; j += stride) t[j] = z;
    uint4* w = reinterpret_cast<uint4*>(g_w16);
    for (size_t j = i; j < (size_t)OUTF * INF / 8; j += stride) w[j] = z;
}

__global__ void scatter_tag(const int* __restrict__ ridx, const int* __restrict__ cidx, int nnz) {
    int i = blockIdx.x * blockDim.x + threadIdx.x;
    if (i < nnz) {
        size_t pos = (size_t)ridx[i] * INF + cidx[i];
        atomicMax(&g_tag[pos], i + 1);
    }
}

__global__ void scatter_write(const int* __restrict__ ridx, const int* __restrict__ cidx,
                              const float* __restrict__ w, int nnz) {
    int i = blockIdx.x * blockDim.x + threadIdx.x;
    if (i < nnz) {
        size_t pos = (size_t)ridx[i] * INF + cidx[i];
        if (g_tag[pos] == i + 1) g_w16[pos] = __float2half_rn(w[i]);
    }
}

__global__ void convert_x(const float* __restrict__ x) {
    size_t stride = (size_t)gridDim.x * blockDim.x;
    size_t n4 = (size_t)TOKENS * INF / 4;
    const float4* xv = reinterpret_cast<const float4*>(x);
    __half2* xo = reinterpret_cast<__half2*>(g_x16);
    for (size_t j = (size_t)blockIdx.x * blockDim.x + threadIdx.x; j < n4; j += stride) {
        float4 v = xv[j];
        xo[2 * j + 0] = __floats2half2_rn(v.x, v.y);
        xo[2 * j + 1] = __floats2half2_rn(v.z, v.w);
    }
}

// ---------------- GEMM: out[m,n] = sum_k x16[m,k]*w16[n,k] + bias[n] ----------------
// 256 threads = 8 warps in 4(m) x 2(n); warp tile 64x64 via m16n8k16.
__global__ void __launch_bounds__(256)
gemm_kernel(const float* __restrict__ bias, float* __restrict__ out) {
    extern __shared__ char smem_raw[];
    uint32_t sbase = (smem_u32(smem_raw) + 1023u) & ~1023u;

    const int tid  = threadIdx.x;
    const int lane = tid & 31;
    const int wid  = tid >> 5;
    const int warp_m = wid & 3;   // 0..3  -> 64 rows each
    const int warp_n = wid >> 2;  // 0..1  -> 64 cols each

    // raster: 32 m-tiles x 32 n-tiles; groups of 8 n-tiles (256 CTAs).
    // within a group consecutive CTAs sweep bm -> B panel (8 MB) L2-resident.
    const int bid = blockIdx.x;
    const int grp = bid >> 8;
    const int idx = bid & 255;
    const int bm = idx & 31;
    const int bn = (grp << 3) + (idx >> 5);

    const __half* Abase = g_x16 + (size_t)bm * BM * INF;
    const __half* Bbase = g_w16 + (size_t)bn * BN * INF;

    float acc[4][8][4];
    #pragma unroll
    for (int i = 0; i < 4; ++i)
        #pragma unroll
        for (int j = 0; j < 8; ++j)
            #pragma unroll
            for (int k = 0; k < 4; ++k) acc[i][j][k] = 0.f;

    auto fill_stage = [&](int stage, int kblk) {
        const int k0 = kblk * BK;
        uint32_t sa = sbase + stage * STAGE_BYTES;
        // A: 256 rows x 128 B -> 2048 x 16B chunks, 8 per thread
        #pragma unroll
        for (int q = tid; q < (BM * BK * 2) / 16; q += 256) {
            int r = q >> 3, cb = (q & 7) * 16;
            cp_async16(sa + SWZ(r * 128 + cb), Abase + (size_t)r * INF + k0 + (q & 7) * 8);
        }
        uint32_t sb = sa + A_BYTES;
        // B: 128 rows x 128 B -> 1024 chunks, 4 per thread
        #pragma unroll
        for (int q = tid; q < (BN * BK * 2) / 16; q += 256) {
            int r = q >> 3, cb = (q & 7) * 16;
            cp_async16(sb + SWZ(r * 128 + cb), Bbase + (size_t)r * INF + k0 + (q & 7) * 8);
        }
    };

    // prologue
    #pragma unroll
    for (int b = 0; b < STAGES - 1; ++b) { fill_stage(b, b); CP_COMMIT(); }

    // ldmatrix lane address components (within tile, pre-swizzle)
    const int a_row_l = ((lane >> 3) & 1) * 8 + (lane & 7);  // m within 16
    const int a_koff  = ((lane >> 4) & 1) * 8;               // k within 16
    const int b_row_l = ((lane >> 4) & 1) * 8 + (lane & 7);  // n within 16
    const int b_koff  = ((lane >> 3) & 1) * 8;               // k within 16

    for (int c = 0; c < KITERS; ++c) {
        CP_WAIT(STAGES - 2);
        __syncthreads();

        const int nf = c + STAGES - 1;
        if (nf < KITERS) fill_stage(nf & (STAGES - 1), nf);
        CP_COMMIT();

        const int sc = c & (STAGES - 1);
        uint32_t sa = sbase + sc * STAGE_BYTES;
        uint32_t sb = sa + A_BYTES;

        #pragma unroll
        for (int ks = 0; ks < BK / 16; ++ks) {
            uint32_t afr[4][4];
            #pragma unroll
            for (int mt = 0; mt < 4; ++mt) {
                int row = warp_m * 64 + mt * 16 + a_row_l;
                int col = ks * 16 + a_koff;
                ldsm_x4(afr[mt], sa + SWZ(row * 128 + col * 2));
            }
            uint32_t bfr[4][4];
            #pragma unroll
            for (int h = 0; h < 4; ++h) {
                int row = warp_n * 64 + h * 16 + b_row_l;
                int col = ks * 16 + b_koff;
                ldsm_x4(bfr[h], sb + SWZ(row * 128 + col * 2));
            }
            #pragma unroll
            for (int mt = 0; mt < 4; ++mt)
                #pragma unroll
                for (int nt = 0; nt < 8; ++nt)
                    mma16816(acc[mt][nt], afr[mt],
                             bfr[nt >> 1][(nt & 1) * 2], bfr[nt >> 1][(nt & 1) * 2 + 1]);
        }
    }

    // epilogue: fused bias, float2 stores
    const int gr = lane >> 2;        // 0..7
    const int gc = (lane & 3) * 2;   // 0,2,4,6
    #pragma unroll
    for (int mt = 0; mt < 4; ++mt) {
        int row0 = bm * BM + warp_m * 64 + mt * 16 + gr;
        #pragma unroll
        for (int nt = 0; nt < 8; ++nt) {
            int col = bn * BN + warp_n * 64 + nt * 8 + gc;
            float2 b2 = *reinterpret_cast<const float2*>(bias + col);
            float2 v0 = {acc[mt][nt][0] + b2.x, acc[mt][nt][1] + b2.y};
            float2 v1 = {acc[mt][nt][2] + b2.x, acc[mt][nt][3] + b2.y};
            *reinterpret_cast<float2*>(out + (size_t)row0 * OUTF + col) = v0;
            *reinterpret_cast<float2*>(out + (size_t)(row0 + 8) * OUTF + col) = v1;
        }
    }
}

// ---------------- launch ----------------
extern "C" void kernel_launch(void* const* d_in, const int* in_sizes, int n_in,
                              void* d_out, int out_size) {
    const float* x    = (const float*)d_in[0];
    const float* w    = (const float*)d_in[1];
    const float* bias = (const float*)d_in[2];
    const int*   ridx = (const int*)d_in[3];
    const int*   cidx = (const int*)d_in[4];
    float* out = (float*)d_out;
    const int nnz = in_sizes[1];

    cudaFuncSetAttribute(gemm_kernel, cudaFuncAttributeMaxDynamicSharedMemorySize, SMEM_DYN);

    prep_zero<<<1024, 256>>>();
    scatter_tag<<<(nnz + 255) / 256, 256>>>(ridx, cidx, nnz);
    scatter_write<<<(nnz + 255) / 256, 256>>>(ridx, cidx, w, nnz);
    convert_x<<<2048, 256>>>(x);

    dim3 grid((TOKENS / BM) * (OUTF / BN));   // 32 * 32 = 1024 CTAs
    gemm_kernel<<<grid, 256, SMEM_DYN>>>(bias, out);
}

// round 4
// speedup vs baseline: 1.1920x; 1.1280x over previous
#include <cuda_runtime.h>
#include <cuda_fp16.h>
#include <cstdint>

// ---------------- problem constants ----------------
#define TOKENS 8192
#define INF    4096
#define OUTF   4096

// ---------------- GEMM tiling ----------------
#define BM 256
#define BN 128
#define BK 64
#define STAGES 4
#define KITERS (INF / BK)                  // 64
#define A_BYTES (BM * BK * 2)              // 32 KB
#define B_BYTES (BN * BK * 2)              // 16 KB
#define STAGE_BYTES (A_BYTES + B_BYTES)    // 48 KB
#define SMEM_DYN (STAGES * STAGE_BYTES + 1024)   // ~193 KB
#define NTILES ((TOKENS / BM) * (OUTF / BN))     // 1024

// ---------------- device scratch (statics, no allocs) ----------------
static __device__ __half g_x16[(size_t)TOKENS * INF];  // 64 MB
static __device__ __half g_w16[(size_t)OUTF * INF];    // 32 MB
static __device__ int    g_tag[(size_t)OUTF * INF];    // 64 MB
static __device__ unsigned g_ticket;

// ---------------- helpers ----------------
__device__ __forceinline__ uint32_t smem_u32(const void* p) {
    uint32_t a;
    asm("{ .reg .u64 t; cvta.to.shared.u64 t, %1; cvt.u32.u64 %0, t; }"
        : "=r"(a) : "l"(p));
    return a;
}

#define SWZ(o) ((o) ^ (((o) >> 3) & 0x70))

__device__ __forceinline__ void cp_async16(uint32_t saddr, const void* gptr) {
    uint64_t g = __cvta_generic_to_global((void*)gptr);
    asm volatile("cp.async.cg.shared.global [%0], [%1], 16;" :: "r"(saddr), "l"(g) : "memory");
}
#define CP_COMMIT() asm volatile("cp.async.commit_group;" ::: "memory")
#define CP_WAIT(n)  asm volatile("cp.async.wait_group %0;" :: "n"(n) : "memory")

__device__ __forceinline__ void ldsm_x4(uint32_t (&r)[4], uint32_t addr) {
    asm volatile("ldmatrix.sync.aligned.m8n8.x4.shared.b16 {%0,%1,%2,%3}, [%4];"
                 : "=r"(r[0]), "=r"(r[1]), "=r"(r[2]), "=r"(r[3]) : "r"(addr));
}

__device__ __forceinline__ void mma16816(float (&d)[4], const uint32_t (&a)[4],
                                         uint32_t b0, uint32_t b1) {
    asm volatile(
        "mma.sync.aligned.m16n8k16.row.col.f32.f16.f16.f32 "
        "{%0,%1,%2,%3}, {%4,%5,%6,%7}, {%8,%9}, {%0,%1,%2,%3};"
        : "+f"(d[0]), "+f"(d[1]), "+f"(d[2]), "+f"(d[3])
        : "r"(a[0]), "r"(a[1]), "r"(a[2]), "r"(a[3]), "r"(b0), "r"(b1));
}

__device__ __forceinline__ void stcs_f2(float* p, float x, float y) {
    asm volatile("st.global.cs.v2.f32 [%0], {%1, %2};"
                 :: "l"(p), "f"(x), "f"(y) : "memory");
}

// ---------------- prep kernels ----------------
// fused: reset ticket, zero tag+w16, convert x -> fp16
__global__ void prep_fused(const float* __restrict__ x) {
    if (blockIdx.x == 0 && threadIdx.x == 0) g_ticket = 0u;
    size_t stride = (size_t)gridDim.x * blockDim.x;
    size_t i = (size_t)blockIdx.x * blockDim.x + threadIdx.x;
    uint4 z = {0u, 0u, 0u, 0u};
    uint4* t = reinterpret_cast<uint4*>(g_tag);
    for (size_t j = i; j < (size_t)OUTF * INF / 4; j += stride) t[j] = z;
    uint4* w = reinterpret_cast<uint4*>(g_w16);
    for (size_t j = i; j < (size_t)OUTF * INF / 8; j += stride) w[j] = z;
    const float4* xv = reinterpret_cast<const float4*>(x);
    __half2* xo = reinterpret_cast<__half2*>(g_x16);
    for (size_t j = i; j < (size_t)TOKENS * INF / 4; j += stride) {
        float4 v = xv[j];
        xo[2 * j + 0] = __floats2half2_rn(v.x, v.y);
        xo[2 * j + 1] = __floats2half2_rn(v.z, v.w);
    }
}

__global__ void scatter_tag(const int* __restrict__ ridx, const int* __restrict__ cidx, int nnz) {
    int i = blockIdx.x * blockDim.x + threadIdx.x;
    if (i < nnz) {
        size_t pos = (size_t)ridx[i] * INF + cidx[i];
        atomicMax(&g_tag[pos], i + 1);
    }
}

__global__ void scatter_write(const int* __restrict__ ridx, const int* __restrict__ cidx,
                              const float* __restrict__ w, int nnz) {
    int i = blockIdx.x * blockDim.x + threadIdx.x;
    if (i < nnz) {
        size_t pos = (size_t)ridx[i] * INF + cidx[i];
        if (g_tag[pos] == i + 1) g_w16[pos] = __float2half_rn(w[i]);
    }
}

// ---------------- GEMM fill helpers ----------------
__device__ __forceinline__ void fill_full(uint32_t sbase, int stage, int kblk,
                                          const __half* Ab, const __half* Bb, int tid) {
    const int k0 = kblk * BK;
    uint32_t sa = sbase + stage * STAGE_BYTES;
    #pragma unroll
    for (int j = 0; j < 8; ++j) {
        int q = tid + j * 256; int r = q >> 3, cb = (q & 7) * 16;
        cp_async16(sa + SWZ(r * 128 + cb), Ab + (size_t)r * INF + k0 + (q & 7) * 8);
    }
    uint32_t sb = sa + A_BYTES;
    #pragma unroll
    for (int j = 0; j < 4; ++j) {
        int q = tid + j * 256; int r = q >> 3, cb = (q & 7) * 16;
        cp_async16(sb + SWZ(r * 128 + cb), Bb + (size_t)r * INF + k0 + (q & 7) * 8);
    }
}

// one quarter (3 of 12 chunks) of a stage fill — spread across ks chunks
__device__ __forceinline__ void fill_part(uint32_t sbase, int stage, int kblk, int part,
                                          const __half* Ab, const __half* Bb, int tid) {
    const int k0 = kblk * BK;
    uint32_t sa = sbase + stage * STAGE_BYTES;
    #pragma unroll
    for (int jj = 0; jj < 2; ++jj) {
        int q = tid + (2 * part + jj) * 256; int r = q >> 3, cb = (q & 7) * 16;
        cp_async16(sa + SWZ(r * 128 + cb), Ab + (size_t)r * INF + k0 + (q & 7) * 8);
    }
    {
        int q = tid + part * 256; int r = q >> 3, cb = (q & 7) * 16;
        cp_async16(sa + A_BYTES + SWZ(r * 128 + cb), Bb + (size_t)r * INF + k0 + (q & 7) * 8);
    }
}

// ---------------- GEMM: out[m,n] = sum_k x16[m,k]*w16[n,k] + bias[n] ----------------
// persistent CTAs, ticketed tiles; 8 warps 4(m)x2(n), warp tile 64x64.
__global__ void __launch_bounds__(256)
gemm_kernel(const float* __restrict__ bias, float* __restrict__ out) {
    extern __shared__ char smem_raw[];
    __shared__ int s_tile;
    uint32_t sbase = (smem_u32(smem_raw) + 1023u) & ~1023u;

    const int tid  = threadIdx.x;
    const int lane = tid & 31;
    const int wid  = tid >> 5;
    const int warp_m = wid & 3;   // 0..3 -> 64 rows each
    const int warp_n = wid >> 2;  // 0..1 -> 64 cols each

    // ldmatrix lane address components
    const int a_row_l = ((lane >> 3) & 1) * 8 + (lane & 7);
    const int a_koff  = ((lane >> 4) & 1) * 8;
    const int b_row_l = ((lane >> 4) & 1) * 8 + (lane & 7);
    const int b_koff  = ((lane >> 3) & 1) * 8;

    float acc[4][8][4];
    #pragma unroll
    for (int i = 0; i < 4; ++i)
        #pragma unroll
        for (int j = 0; j < 8; ++j)
            #pragma unroll
            for (int k = 0; k < 4; ++k) acc[i][j][k] = 0.f;

    auto map_tile = [](int tt, const __half*& A, const __half*& B, int& m, int& n) {
        // groups of 8 bn x 32 bm = 256 tiles -> B panel (8 MB) stays L2-resident
        int grp = tt >> 8, idx = tt & 255;
        m = idx & 31;
        n = (grp << 3) | (idx >> 5);
        A = g_x16 + (size_t)m * BM * INF;
        B = g_w16 + (size_t)n * BN * INF;
    };

    // first ticket
    if (tid == 0) s_tile = (int)atomicAdd(&g_ticket, 1u);
    __syncthreads();
    int t = s_tile;
    if (t >= NTILES) return;

    int bm, bn;
    const __half *Ab, *Bb;
    map_tile(t, Ab, Bb, bm, bn);

    // prologue: stages 0..2
    fill_full(sbase, 0, 0, Ab, Bb, tid); CP_COMMIT();
    fill_full(sbase, 1, 1, Ab, Bb, tid); CP_COMMIT();
    fill_full(sbase, 2, 2, Ab, Bb, tid); CP_COMMIT();

    while (true) {
        // grab next ticket early (latency hidden behind k-loop)
        if (tid == 0) s_tile = (int)atomicAdd(&g_ticket, 1u);

        for (int c = 0; c < KITERS; ++c) {
            CP_WAIT(2);
            __syncthreads();

            const int sc = c & (STAGES - 1);
            uint32_t sa = sbase + sc * STAGE_BYTES;
            uint32_t sb = sa + A_BYTES;
            const bool do_fill = (c < KITERS - 3);
            const int  nstage  = (c + 3) & (STAGES - 1);

            #pragma unroll
            for (int ks = 0; ks < BK / 16; ++ks) {
                if (do_fill) fill_part(sbase, nstage, c + 3, ks, Ab, Bb, tid);

                uint32_t afr[4][4];
                #pragma unroll
                for (int mt = 0; mt < 4; ++mt) {
                    int row = warp_m * 64 + mt * 16 + a_row_l;
                    int col = ks * 16 + a_koff;
                    ldsm_x4(afr[mt], sa + SWZ(row * 128 + col * 2));
                }
                uint32_t bfr[4][4];
                #pragma unroll
                for (int h = 0; h < 4; ++h) {
                    int row = warp_n * 64 + h * 16 + b_row_l;
                    int col = ks * 16 + b_koff;
                    ldsm_x4(bfr[h], sb + SWZ(row * 128 + col * 2));
                }
                #pragma unroll
                for (int mt = 0; mt < 4; ++mt)
                    #pragma unroll
                    for (int nt = 0; nt < 8; ++nt)
                        mma16816(acc[mt][nt], afr[mt],
                                 bfr[nt >> 1][(nt & 1) * 2], bfr[nt >> 1][(nt & 1) * 2 + 1]);
            }
            CP_COMMIT();
        }

        __syncthreads();                 // compute done; s_tile visible
        const int tn = s_tile;

        // issue NEXT tile's prologue before the epilogue (stages 0..2 are free)
        int bm2 = 0, bn2 = 0;
        const __half *Ab2 = nullptr, *Bb2 = nullptr;
        if (tn < NTILES) {
            map_tile(tn, Ab2, Bb2, bm2, bn2);
            fill_full(sbase, 0, 0, Ab2, Bb2, tid); CP_COMMIT();
            fill_full(sbase, 1, 1, Ab2, Bb2, tid); CP_COMMIT();
            fill_full(sbase, 2, 2, Ab2, Bb2, tid); CP_COMMIT();
        }

        // epilogue: fused bias, streaming float2 stores
        {
            const int gr = lane >> 2;
            const int gc = (lane & 3) * 2;
            #pragma unroll
            for (int mt = 0; mt < 4; ++mt) {
                int row0 = bm * BM + warp_m * 64 + mt * 16 + gr;
                #pragma unroll
                for (int nt = 0; nt < 8; ++nt) {
                    int col = bn * BN + warp_n * 64 + nt * 8 + gc;
                    float2 b2 = *reinterpret_cast<const float2*>(bias + col);
                    stcs_f2(out + (size_t)row0 * OUTF + col,
                            acc[mt][nt][0] + b2.x, acc[mt][nt][1] + b2.y);
                    stcs_f2(out + (size_t)(row0 + 8) * OUTF + col,
                            acc[mt][nt][2] + b2.x, acc[mt][nt][3] + b2.y);
                    acc[mt][nt][0] = 0.f; acc[mt][nt][1] = 0.f;
                    acc[mt][nt][2] = 0.f; acc[mt][nt][3] = 0.f;
                }
            }
        }

        if (tn >= NTILES) break;
        t = tn; bm = bm2; bn = bn2; Ab = Ab2; Bb = Bb2;
    }
}

// ---------------- launch ----------------
extern "C" void kernel_launch(void* const* d_in, const int* in_sizes, int n_in,
                              void* d_out, int out_size) {
    const float* x    = (const float*)d_in[0];
    const float* w    = (const float*)d_in[1];
    const float* bias = (const float*)d_in[2];
    const int*   ridx = (const int*)d_in[3];
    const int*   cidx = (const int*)d_in[4];
    float* out = (float*)d_out;
    const int nnz = in_sizes[1];

    cudaFuncSetAttribute(gemm_kernel, cudaFuncAttributeMaxDynamicSharedMemorySize, SMEM_DYN);

    prep_fused<<<2048, 256>>>(x);
    scatter_tag<<<(nnz + 255) / 256, 256>>>(ridx, cidx, nnz);
    scatter_write<<<(nnz + 255) / 256, 256>>>(ridx, cidx, w, nnz);

    // persistent grid: ticketing makes extra CTAs exit immediately on 148- or 152-SM parts
    gemm_kernel<<<160, 256, SMEM_DYN>>>(bias, out);
}